// round 9
// baseline (speedup 1.0000x reference)
#include <cuda_runtime.h>
#include <cuda_fp16.h>
#include <cstdint>

#define NN 100000
#define NE 3200000
#define DEG_SCALE 33554432.0f   // 2^25 fixed-point for packed degree

// ---------------- scratch (device globals; no allocation allowed) ----------
__device__ __align__(16) unsigned long long g_pack[NN]; // {cnt<<40 | deg*2^25}
__device__ __align__(16) float g_dinv[NN];
__device__ __align__(16) int   g_cnt[NN];
__device__ __align__(16) int   g_off[NN];
__device__ __align__(16) int   g_cur[NN];
__device__ __align__(16) int   g_bsum[512];
__device__ int g_is64;

__device__ __align__(16) uint2 g_edge[NE];      // CSR: {src, norm as half2 dup}

__device__ __align__(16) __half g_t1h[NN * 32]; // x @ W1
__device__ __align__(16) __half g_h1h[NN * 32]; // elu layer-1 out
__device__ __align__(16) __half g_s2h[NN * 32]; // A @ h1
__device__ __align__(16) __half g_h2h[NN * 64]; // elu layer-2 out
__device__ __align__(16) __half g_s3h[NN * 64]; // A @ h2

// ---------------- init + dtype detect (merged) -----------------------------
__global__ void k_init(const int* __restrict__ ei32, int n) {
    if (blockIdx.x == 0) {
        __shared__ int cnt;
        if (threadIdx.x == 0) cnt = 0;
        __syncthreads();
        int zeros = 0;
        for (int i = threadIdx.x; i < 1024; i += blockDim.x)
            if (ei32[2 * i + 1] == 0) zeros++;
        atomicAdd(&cnt, zeros);
        __syncthreads();
        if (threadIdx.x == 0) g_is64 = (cnt > 900) ? 1 : 0;
    }
    int i = blockIdx.x * blockDim.x + threadIdx.x;
    if (i < n) g_pack[i] = (unsigned long long)DEG_SCALE;  // deg=1 (self), cnt=0
}

__device__ __forceinline__ void load_edge(const int* __restrict__ ei32,
                                          int e, int E, int n, int& r, int& c) {
    if (g_is64) {
        r = ei32[2 * (long long)e];
        c = ei32[2 * ((long long)E + e)];
    } else {
        r = ei32[e];
        c = ei32[E + e];
    }
    if ((unsigned)r >= (unsigned)n) r = 0;
    if ((unsigned)c >= (unsigned)n) c = 0;
}

__global__ void k_prep(const int* __restrict__ ei32,
                       const float* __restrict__ ea, int E, int n) {
    int e = blockIdx.x * blockDim.x + threadIdx.x;
    if (e >= E) return;
    int c;
    if (g_is64) c = ei32[2 * ((long long)E + e)];
    else        c = ei32[E + e];
    if ((unsigned)c >= (unsigned)n) c = 0;
    const unsigned long long add =
        (1ULL << 40) | (unsigned long long)(fmaxf(ea[e], 0.f) * DEG_SCALE + 0.5f);
    atomicAdd(&g_pack[c], add);
}

__global__ void k_dinv(int n) {
    int i = blockIdx.x * blockDim.x + threadIdx.x;
    if (i >= n) return;
    const unsigned long long p = g_pack[i];
    g_cnt[i] = (int)(p >> 40);
    const float d = (float)(p & 0xFFFFFFFFFFULL) * (1.0f / DEG_SCALE);
    g_dinv[i] = (d > 0.0f) ? rsqrtf(fmaxf(d, 1e-30f)) : 0.0f;
}

// ---------------- 3-kernel exclusive scan of g_cnt -> g_off/g_cur ----------
__global__ void k_scan1(int n) {
    __shared__ int sh[256];
    const int t = threadIdx.x;
    const int i = blockIdx.x * 256 + t;
    int v = (i < n) ? g_cnt[i] : 0;
    sh[t] = v;
    __syncthreads();
    for (int d = 1; d < 256; d <<= 1) {
        int u = (t >= d) ? sh[t - d] : 0;
        __syncthreads();
        sh[t] += u;
        __syncthreads();
    }
    if (i < n) g_off[i] = sh[t] - v;
    if (t == 255) g_bsum[blockIdx.x] = sh[255];
}

__global__ void k_scan2(int nb) {
    __shared__ int sh[512];
    const int t = threadIdx.x;
    int v = (t < nb) ? g_bsum[t] : 0;
    sh[t] = v;
    __syncthreads();
    for (int d = 1; d < 512; d <<= 1) {
        int u = (t >= d) ? sh[t - d] : 0;
        __syncthreads();
        sh[t] += u;
        __syncthreads();
    }
    if (t < nb) g_bsum[t] = sh[t] - v;
}

__global__ void k_scan3(int n) {
    int i = blockIdx.x * 256 + threadIdx.x;
    if (i < n) {
        const int o = g_off[i] + g_bsum[blockIdx.x];
        g_off[i] = o;
        g_cur[i] = o;
    }
}

// ---------------- CSR fill: payload {src, half2(norm,norm)} ----------------
__global__ void k_fill(const int* __restrict__ ei32,
                       const float* __restrict__ ea, int E, int n) {
    int e = blockIdx.x * blockDim.x + threadIdx.x;
    if (e >= E) return;
    int r, c;
    load_edge(ei32, e, E, n, r, c);
    const int pos = atomicAdd(&g_cur[c], 1);
    const float w = g_dinv[r] * ea[e] * g_dinv[c];
    const unsigned hb = (unsigned)__half_as_ushort(__float2half(w));
    g_edge[pos] = make_uint2((unsigned)r, hb | (hb << 16));
}

// ---------------- register-tiled GEMM with fused epilogue -------------------
// 256 threads; thread tile = 4 nodes x 4 fouts; X staged transposed in smem.
__device__ __forceinline__ float to_f32(float v) { return v; }
__device__ __forceinline__ float to_f32(__half v) { return __half2float(v); }

template <int FIN, int FOUT, bool BIAS, bool ELU, bool WF, bool WH, typename IT>
__global__ void k_gemm(const IT* __restrict__ X, const float* __restrict__ W,
                       const float* __restrict__ b, float* __restrict__ Yf,
                       __half* __restrict__ Yh, int n) {
    constexpr int BX   = FOUT / 4;
    constexpr int BY   = 256 / BX;
    constexpr int NPB  = BY * 4;
    constexpr int KC   = 32;
    constexpr int XSTR = NPB + 1;

    __shared__ float Xs[KC * XSTR];
    __shared__ float Ws[KC * FOUT];

    const int tid = threadIdx.x;
    const int tx = tid % BX;
    const int ty = tid / BX;
    const int node0 = blockIdx.x * NPB;

    float acc[4][4] = {};

    for (int ck = 0; ck < FIN; ck += KC) {
#pragma unroll
        for (int t = 0; t < NPB * KC / 256; t++) {
            const int idx = t * 256 + tid;
            const int ln = idx / KC;
            const int k  = idx % KC;
            const int node = node0 + ln;
            Xs[k * XSTR + ln] =
                (node < n) ? to_f32(X[(size_t)node * FIN + ck + k]) : 0.f;
        }
#pragma unroll
        for (int t = 0; t < KC * FOUT / 256; t++) {
            const int idx = t * 256 + tid;
            Ws[idx] = W[(size_t)(ck + idx / FOUT) * FOUT + (idx % FOUT)];
        }
        __syncthreads();

#pragma unroll
        for (int k = 0; k < KC; k++) {
            const float4 wv = *(const float4*)&Ws[k * FOUT + tx * 4];
#pragma unroll
            for (int j = 0; j < 4; j++) {
                const float xv = Xs[k * XSTR + ty * 4 + j];
                acc[j][0] += xv * wv.x;
                acc[j][1] += xv * wv.y;
                acc[j][2] += xv * wv.z;
                acc[j][3] += xv * wv.w;
            }
        }
        __syncthreads();
    }

    float4 bv = make_float4(0.f, 0.f, 0.f, 0.f);
    if (BIAS) bv = *(const float4*)&b[tx * 4];

#pragma unroll
    for (int j = 0; j < 4; j++) {
        const int node = node0 + ty * 4 + j;
        if (node >= n) continue;
        float o0 = acc[j][0] + bv.x;
        float o1 = acc[j][1] + bv.y;
        float o2 = acc[j][2] + bv.z;
        float o3 = acc[j][3] + bv.w;
        if (ELU) {
            o0 = (o0 > 0.f) ? o0 : expm1f(o0);
            o1 = (o1 > 0.f) ? o1 : expm1f(o1);
            o2 = (o2 > 0.f) ? o2 : expm1f(o2);
            o3 = (o3 > 0.f) ? o3 : expm1f(o3);
        }
        if (WF) {
            float4 ov; ov.x = o0; ov.y = o1; ov.z = o2; ov.w = o3;
            *(float4*)(Yf + (size_t)node * FOUT + tx * 4) = ov;
        }
        if (WH) {
            __half2* hp = (__half2*)(Yh + (size_t)node * FOUT + tx * 4);
            hp[0] = __floats2half2_rn(o0, o1);
            hp[1] = __floats2half2_rn(o2, o3);
        }
    }
}

// ---------------- fused CSR aggregate ---------------------------------------
// out[i] = sum_{e in seg(i)} gh[src(e)]*norm(e) + gh[i]*dinv[i]^2 (+b, elu)
// F/8 lanes per node, 16B gathers, paired uint4 meta loads, HFMA2 inner math.
template <int F, bool BE>
__global__ void k_agg(const __half* __restrict__ gh, const float* __restrict__ b,
                      __half* __restrict__ outh, int n) {
    constexpr int LPE = F / 8;
    const long long tid = (long long)blockIdx.x * blockDim.x + threadIdx.x;
    const int node = (int)(tid / LPE);
    const int s = (int)(tid % LPE);
    if (node >= n) return;

    const __half* __restrict__ tbl = gh + s * 8;
    const int end = g_off[node] + g_cnt[node];
    int p = g_off[node];

    float a0 = 0.f, a1 = 0.f, a2 = 0.f, a3 = 0.f;
    float a4 = 0.f, a5 = 0.f, a6 = 0.f, a7 = 0.f;

    // scalar fp32 path for head/tail edges
#define GATH_S(SRC, WB)                                                        \
    {                                                                          \
        const float w_ = __low2float(*(const __half2*)&(WB));                  \
        const uint4 raw_ = *(const uint4*)(tbl + (size_t)(SRC) * F);           \
        const float2 p0_ = __half22float2(*(const __half2*)&raw_.x);           \
        const float2 p1_ = __half22float2(*(const __half2*)&raw_.y);           \
        const float2 p2_ = __half22float2(*(const __half2*)&raw_.z);           \
        const float2 p3_ = __half22float2(*(const __half2*)&raw_.w);           \
        a0 += p0_.x * w_; a1 += p0_.y * w_;                                    \
        a2 += p1_.x * w_; a3 += p1_.y * w_;                                    \
        a4 += p2_.x * w_; a5 += p2_.y * w_;                                    \
        a6 += p3_.x * w_; a7 += p3_.y * w_;                                    \
    }
    // half2 path: 4 hfma2 per edge into half2 accumulators
#define GATH_H(SRC, WB)                                                        \
    {                                                                          \
        const __half2 w2_ = *(const __half2*)&(WB);                            \
        const uint4 raw_ = *(const uint4*)(tbl + (size_t)(SRC) * F);           \
        c0 = __hfma2(*(const __half2*)&raw_.x, w2_, c0);                       \
        c1 = __hfma2(*(const __half2*)&raw_.y, w2_, c1);                       \
        c2 = __hfma2(*(const __half2*)&raw_.z, w2_, c2);                       \
        c3 = __hfma2(*(const __half2*)&raw_.w, w2_, c3);                       \
    }

    // align p to even index for 16B meta loads
    if ((p & 1) && p < end) {
        const uint2 e0 = g_edge[p];
        GATH_S(e0.x, e0.y)
        p++;
    }
    // main: 4 edges per iter = 2 x 16B meta loads
    for (; p + 4 <= end; p += 4) {
        const uint4 m0 = *(const uint4*)&g_edge[p];
        const uint4 m1 = *(const uint4*)&g_edge[p + 2];
        __half2 c0 = __floats2half2_rn(0.f, 0.f);
        __half2 c1 = c0, c2 = c0, c3 = c0;
        GATH_H(m0.x, m0.y)
        GATH_H(m0.z, m0.w)
        GATH_H(m1.x, m1.y)
        GATH_H(m1.z, m1.w)
        const float2 f0 = __half22float2(c0);
        const float2 f1 = __half22float2(c1);
        const float2 f2 = __half22float2(c2);
        const float2 f3 = __half22float2(c3);
        a0 += f0.x; a1 += f0.y; a2 += f1.x; a3 += f1.y;
        a4 += f2.x; a5 += f2.y; a6 += f3.x; a7 += f3.y;
    }
    // tail
    for (; p < end; p++) {
        const uint2 e0 = g_edge[p];
        GATH_S(e0.x, e0.y)
    }
#undef GATH_S
#undef GATH_H

    // self-loop (fp32 path)
    float dv = g_dinv[node]; dv *= dv;
    {
        const uint4 raw = *(const uint4*)(tbl + (size_t)node * F);
        const float2 p0 = __half22float2(*(const __half2*)&raw.x);
        const float2 p1 = __half22float2(*(const __half2*)&raw.y);
        const float2 p2 = __half22float2(*(const __half2*)&raw.z);
        const float2 p3 = __half22float2(*(const __half2*)&raw.w);
        a0 += p0.x * dv; a1 += p0.y * dv;
        a2 += p1.x * dv; a3 += p1.y * dv;
        a4 += p2.x * dv; a5 += p2.y * dv;
        a6 += p3.x * dv; a7 += p3.y * dv;
    }
    if (BE) {
        a0 += b[s * 8 + 0]; a1 += b[s * 8 + 1];
        a2 += b[s * 8 + 2]; a3 += b[s * 8 + 3];
        a4 += b[s * 8 + 4]; a5 += b[s * 8 + 5];
        a6 += b[s * 8 + 6]; a7 += b[s * 8 + 7];
        a0 = (a0 > 0.f) ? a0 : expm1f(a0);
        a1 = (a1 > 0.f) ? a1 : expm1f(a1);
        a2 = (a2 > 0.f) ? a2 : expm1f(a2);
        a3 = (a3 > 0.f) ? a3 : expm1f(a3);
        a4 = (a4 > 0.f) ? a4 : expm1f(a4);
        a5 = (a5 > 0.f) ? a5 : expm1f(a5);
        a6 = (a6 > 0.f) ? a6 : expm1f(a6);
        a7 = (a7 > 0.f) ? a7 : expm1f(a7);
    }
    __half2* hp = (__half2*)(outh + (size_t)node * F + s * 8);
    hp[0] = __floats2half2_rn(a0, a1);
    hp[1] = __floats2half2_rn(a2, a3);
    hp[2] = __floats2half2_rn(a4, a5);
    hp[3] = __floats2half2_rn(a6, a7);
}

// ---------------- fp32 output variant for the last agg->gemm path ----------
// (not needed; layer-3 agg writes fp16 s3h consumed by fp16-input GEMM)

// ---------------- launch ---------------------------------------------------
static inline int cdiv(long long a, int b) { return (int)((a + b - 1) / b); }

extern "C" void kernel_launch(void* const* d_in, const int* in_sizes, int n_in,
                              void* d_out, int out_size) {
    const float* x  = (const float*)d_in[0];
    const int*   ei = (const int*)d_in[1];
    const float* ea = (const float*)d_in[2];
    const float* W1 = (const float*)d_in[3];
    const float* b1 = (const float*)d_in[4];
    const float* W2 = (const float*)d_in[5];
    const float* b2 = (const float*)d_in[6];
    const float* W3 = (const float*)d_in[7];
    const float* b3 = (const float*)d_in[8];
    float* out = (float*)d_out;

    const int n = in_sizes[0] / 128;   // 100000
    const int E = in_sizes[2];         // 3200000

    void *p_t1h, *p_h1h, *p_s2h, *p_h2h, *p_s3h;
    cudaGetSymbolAddress(&p_t1h, g_t1h);
    cudaGetSymbolAddress(&p_h1h, g_h1h);
    cudaGetSymbolAddress(&p_s2h, g_s2h);
    cudaGetSymbolAddress(&p_h2h, g_h2h);
    cudaGetSymbolAddress(&p_s3h, g_s3h);

    const int T = 256;
    const int nb = cdiv(n, 256);

    // --- prep: degrees, dinv, CSR build ---
    k_init<<<cdiv(n, T), T>>>(ei, n);
    k_prep<<<cdiv(E, T), T>>>(ei, ea, E, n);
    k_dinv<<<cdiv(n, T), T>>>(n);
    k_scan1<<<nb, 256>>>(n);
    k_scan2<<<1, 512>>>(nb);
    k_scan3<<<nb, 256>>>(n);
    k_fill<<<cdiv(E, T), T>>>(ei, ea, E, n);

    // --- layer 1: t1 = x@W1 ; h1 = elu(A t1 + b1) ---
    k_gemm<128, 32, false, false, false, true, float><<<cdiv(n, 128), 256>>>(
        x, W1, nullptr, nullptr, (__half*)p_t1h, n);
    k_agg<32, true><<<cdiv((long long)n * 4, T), T>>>(
        (const __half*)p_t1h, b1, (__half*)p_h1h, n);

    // --- layer 2: s2 = A h1 ; h2 = elu(s2@W2 + b2) ---
    k_agg<32, false><<<cdiv((long long)n * 4, T), T>>>(
        (const __half*)p_h1h, nullptr, (__half*)p_s2h, n);
    k_gemm<32, 64, true, true, false, true, __half><<<cdiv(n, 64), 256>>>(
        (const __half*)p_s2h, W2, b2, nullptr, (__half*)p_h2h, n);

    // --- layer 3: s3 = A h2 ; out = s3@W3 + b3 ---
    k_agg<64, false><<<cdiv((long long)n * 8, T), T>>>(
        (const __half*)p_h2h, nullptr, (__half*)p_s3h, n);
    k_gemm<64, 128, true, false, true, false, __half><<<cdiv(n, 32), 256>>>(
        (const __half*)p_s3h, W3, b3, out, nullptr, n);
}